// round 9
// baseline (speedup 1.0000x reference)
#include <cuda_runtime.h>
#include <cuda_bf16.h>

// Problem constants (fixed by reference: Z=2, N=256, A=14, AA=21, voxel 16^3, RES=1)
namespace {
constexpr int NA   = 14;
constexpr int ZN   = 2 * 256;               // 512 residues
constexpr int VOX  = 16;
constexpr int VOXELS = VOX * VOX * VOX;     // 4096
constexpr size_t BB_BASE  = 0;                                   // (ZN,4,3)
constexpr size_t DIV_BASE = (size_t)ZN * 12;                     // (ZN,1,16,16,16)
constexpr size_t FR_BASE  = DIV_BASE + (size_t)ZN * VOXELS;      // (ZN,3,3)
}

// ---- packed dual-fp32 helpers (SASS FFMA2/FMUL2; two independent IEEE fp32 ops) ----
typedef unsigned long long u64;
__device__ __forceinline__ u64 pk2(float lo, float hi) {
    u64 d; asm("mov.b64 %0, {%1, %2};" : "=l"(d) : "f"(lo), "f"(hi)); return d;
}
__device__ __forceinline__ void upk2(u64 d, float& lo, float& hi) {
    asm("mov.b64 {%0, %1}, %2;" : "=f"(lo), "=f"(hi) : "l"(d));
}
__device__ __forceinline__ u64 fma2(u64 a, u64 b, u64 c) {
    u64 d; asm("fma.rn.f32x2 %0, %1, %2, %3;" : "=l"(d) : "l"(a), "l"(b), "l"(c)); return d;
}
__device__ __forceinline__ u64 mul2(u64 a, u64 b) {
    u64 d; asm("mul.rn.f32x2 %0, %1, %2;" : "=l"(d) : "l"(a), "l"(b)); return d;
}
__device__ __forceinline__ float rcpa(float x) {          // MUFU.RCP approx
    float r; asm("rcp.approx.f32 %0, %1;" : "=f"(r) : "f"(x)); return r;
}

// 2 CTAs per residue (half = low/high 8 y-planes), 128 threads each.
// (128,7): 148*7 = 1036 concurrent CTAs >= 1024 grid -> single wave.
__global__ __launch_bounds__(128, 7)
void pp_kernel(const float* __restrict__ C,
               const int*   __restrict__ Lw,     // int32 view of L (int32 OR int64 storage)
               const float* __restrict__ amask,
               const float* __restrict__ amber,
               float* __restrict__ out)
{
    const int rn   = blockIdx.x >> 1;
    const int half = blockIdx.x & 1;
    const int t    = threadIdx.x;       // local column: y_lo = t>>4, v = t&15

    __shared__ float4 s_atom[NA];       // x,y,z,charge

    const float* Cr = C + (size_t)rn * NA * 3;

    // ---- atom + charge load (threads 0..13) ----
    if (t < NA) {
        // Detect int64-vs-int32 storage of L (values in [-1,20]): for int64 (LE)
        // every odd 32-bit word is 0 or -1; misdetect prob for int32 ~21^-16.
        int bad = 0;
        #pragma unroll
        for (int k = 0; k < 16; ++k) {
            int hv = __ldg(Lw + 2 * k + 1);
            bad |= (hv != 0) & (hv != -1);
        }
        int lv = bad ? __ldg(Lw + rn) : __ldg(Lw + 2 * rn);
        int lc = (lv == -1) ? 20 : lv;       // X_LBL = 20
        float q = __ldg(amber + lc * NA + t) * __ldg(amask + (size_t)rn * NA + t);
        s_atom[t] = make_float4(__ldg(Cr + 3 * t),
                                __ldg(Cr + 3 * t + 1),
                                __ldg(Cr + 3 * t + 2), q);
    }

    // ---- frame build (redundant per thread; broadcast loads; block-uniform) ----
    float n0 = __ldg(Cr + 0), n1 = __ldg(Cr + 1), n2 = __ldg(Cr + 2);
    float a0 = __ldg(Cr + 3), a1 = __ldg(Cr + 4), a2 = __ldg(Cr + 5);
    float c0 = __ldg(Cr + 6), c1 = __ldg(Cr + 7), c2 = __ldg(Cr + 8);

    float b1x = a0 - n0, b1y = a1 - n1, b1z = a2 - n2;
    float b2x = c0 - a0, b2y = c1 - a1, b2z = c2 - a2;
    float b3x = b1y * b2z - b1z * b2y;
    float b3y = b1z * b2x - b1x * b2z;
    float b3z = b1x * b2y - b1y * b2x;
    float cb0 = a0 - 0.58273431f * b2x + 0.56802827f * b1x - 0.54067466f * b3x;
    float cb1 = a1 - 0.58273431f * b2y + 0.56802827f * b1y - 0.54067466f * b3y;
    float cb2 = a2 - 0.58273431f * b2z + 0.56802827f * b1z - 0.54067466f * b3z;

    float yx = cb0 - a0, yy = cb1 - a1, yz = cb2 - a2;
    float yn = sqrtf(yx * yx + yy * yy + yz * yz);
    float yi = 1.0f / fmaxf(yn, 1e-6f);
    float yux = yx * yi, yuy = yy * yi, yuz = yz * yi;

    // scalar projection subtracted from every component (replicates reference)
    float xrx = c0 - n0, xry = c1 - n1, xrz = c2 - n2;
    float xp = xrx * yux + xry * yuy + xrz * yuz;
    float xx = xrx - xp, xy = xry - xp, xz = xrz - xp;
    float xn = sqrtf(xx * xx + xy * xy + xz * xz);
    float xi = 1.0f / fmaxf(xn, 1e-6f);
    float xux = xx * xi, xuy = xy * xi, xuz = xz * xi;

    float zux = xuy * yuz - xuz * yuy;
    float zuy = xuz * yux - xux * yuz;
    float zuz = xux * yuy - xuy * yux;

    if (half == 0 && t == 0) {
        float* bb = out + BB_BASE + (size_t)rn * 12;
        bb[0] = n0;  bb[1] = n1;  bb[2] = n2;
        bb[3] = a0;  bb[4] = a1;  bb[5] = a2;
        bb[6] = c0;  bb[7] = c1;  bb[8] = c2;
        bb[9] = cb0; bb[10] = cb1; bb[11] = cb2;
        float* fr = out + FR_BASE + (size_t)rn * 9;
        fr[0] = xux; fr[1] = xuy; fr[2] = xuz;
        fr[3] = yux; fr[4] = yuy; fr[5] = yuz;
        fr[6] = zux; fr[7] = zuy; fr[8] = zuz;
    }

    __syncthreads();

    // ---- per-thread voxel column base for (y,v); x varies in registers ----
    const int   yidx = half * 8 + (t >> 4);
    const float gy = (float)yidx - 4.0f;       // VY/4
    const float gz = (float)(t & 15) - 8.0f;   // VZ/2
    float px = cb0 + gy * yux + gz * zux;
    float py = cb1 + gy * yuy + gz * zuy;
    float pz = cb2 + gy * yuz + gz * zuz;

    // packed broadcast constants (block-uniform / compile-time -> UR-eligible)
    const u64 xux2 = pk2(xux, xux), xuy2 = pk2(xuy, xuy), xuz2 = pk2(xuz, xuz);
    const u64 eps2 = pk2(1e-30f, 1e-30f);
    u64 gxp[8];
    #pragma unroll
    for (int j = 0; j < 8; ++j)
        gxp[j] = pk2((float)(2 * j) - 8.0f, (float)(2 * j) - 7.0f);

    u64 Fx2[8], Fy2[8], Fz2[8];
    #pragma unroll
    for (int j = 0; j < 8; ++j) { Fx2[j] = 0ull; Fy2[j] = 0ull; Fz2[j] = 0ull; }

    // hot loop: 14 atoms x 8 packed x-pairs.
    // weight: 1/(d*max(d,1)^2) = ry * min(rcp(r2), 1),  ry = rsqrt(r2+eps)
    //   r2>=1: ry*(1/r2) = r2^{-3/2}; r2<1: rcp>1 -> min=1 -> ry. Continuous.
    //   rsqrt and rcp both issue off r2 (parallel MUFU), min rides the ALU
    //   pipe, and only two packed muls hit the FMA pipe (vs six scalar muls).
    #pragma unroll 1
    for (int a = 0; a < NA; ++a) {
        float4 at = s_atom[a];
        float qx = px - at.x, qy = py - at.y, qz = pz - at.z;
        const u64 qx2 = pk2(qx, qx), qy2 = pk2(qy, qy), qz2 = pk2(qz, qz);
        const u64 w0pk = pk2(at.w, at.w);      // block-uniform -> UR
        #pragma unroll
        for (int j = 0; j < 8; ++j) {
            u64 dx2 = fma2(gxp[j], xux2, qx2);
            u64 dy2 = fma2(gxp[j], xuy2, qy2);
            u64 dz2 = fma2(gxp[j], xuz2, qz2);
            u64 r22 = fma2(dx2, dx2, fma2(dy2, dy2, fma2(dz2, dz2, eps2)));
            float ra, rb; upk2(r22, ra, rb);
            float ya = rsqrtf(ra), yb = rsqrtf(rb);   // MUFU
            float ca = rcpa(ra),   cb = rcpa(rb);     // MUFU (parallel with rsqrt)
            float ma = fminf(ca, 1.0f);               // ALU (FMNMX)
            float mb = fminf(cb, 1.0f);
            u64 wp = mul2(mul2(pk2(ya, yb), pk2(ma, mb)), w0pk);
            Fx2[j] = fma2(wp, dx2, Fx2[j]);
            Fy2[j] = fma2(wp, dy2, Fy2[j]);
            Fz2[j] = fma2(wp, dz2, Fz2[j]);
        }
    }

    // ---- normalize field vectors (packed) ----
    #pragma unroll
    for (int j = 0; j < 8; ++j) {
        u64 s2 = fma2(Fx2[j], Fx2[j], fma2(Fy2[j], Fy2[j], mul2(Fz2[j], Fz2[j])));
        float sa, sb; upk2(s2, sa, sb);
        float sca = (sa > 0.0f) ? rsqrtf(sa) : 1.0f;
        float scb = (sb > 0.0f) ? rsqrtf(sb) : 1.0f;
        u64 sc2 = pk2(sca, scb);
        Fx2[j] = mul2(Fx2[j], sc2);
        Fy2[j] = mul2(Fy2[j], sc2);
        Fz2[j] = mul2(Fz2[j], sc2);
    }

    // unpack to scalars for the finite difference
    float Fx[VOX], Fy[VOX], Fz[VOX];
    #pragma unroll
    for (int j = 0; j < 8; ++j) {
        upk2(Fx2[j], Fx[2 * j], Fx[2 * j + 1]);
        upk2(Fy2[j], Fy[2 * j], Fy[2 * j + 1]);
        upk2(Fz2[j], Fz[2 * j], Fz[2 * j + 1]);
    }

    // ---- divergence: all components differenced along the VX axis (axis 2),
    //      x: flip_last=False, y/z: flip_last=True (matches reference) ----
    float* dv = out + DIV_BASE + (size_t)rn * VOXELS + (half * 128 + t);
    dv[0] = (Fx[1] - Fx[0]) + (Fy[1] - Fy[0]) + (Fz[1] - Fz[0]);
    #pragma unroll
    for (int i = 1; i < VOX - 1; ++i) {
        float d = 0.5f * (Fx[i + 1] - Fx[i - 1])
                + 0.5f * (Fy[i + 1] - Fy[i - 1])
                + 0.5f * (Fz[i + 1] - Fz[i - 1]);
        dv[i * 256] = d;
    }
    dv[15 * 256] = (Fx[15] - Fx[14]) + (Fy[14] - Fy[15]) + (Fz[14] - Fz[15]);
}

extern "C" void kernel_launch(void* const* d_in, const int* in_sizes, int n_in,
                              void* d_out, int out_size)
{
    const float* C     = (const float*)d_in[0];
    const int*   Lw    = (const int*)  d_in[1];   // int32 view; width auto-detected
    const float* amask = (const float*)d_in[2];
    // d_in[3] = valid_mask: unused by the reference
    const float* amber = (const float*)d_in[4];

    pp_kernel<<<ZN * 2, 128>>>(C, Lw, amask, amber, (float*)d_out);
}

// round 10
// speedup vs baseline: 1.2471x; 1.2471x over previous
#include <cuda_runtime.h>
#include <cuda_bf16.h>

// Problem constants (fixed by reference: Z=2, N=256, A=14, AA=21, voxel 16^3, RES=1)
namespace {
constexpr int NA   = 14;
constexpr int ZN   = 2 * 256;               // 512 residues
constexpr int VOX  = 16;
constexpr int VOXELS = VOX * VOX * VOX;     // 4096
constexpr size_t BB_BASE  = 0;                                   // (ZN,4,3)
constexpr size_t DIV_BASE = (size_t)ZN * 12;                     // (ZN,1,16,16,16)
constexpr size_t FR_BASE  = DIV_BASE + (size_t)ZN * VOXELS;      // (ZN,3,3)

// gx pair constants as raw u64 bit patterns: (float)(2j-8) in lo, (2j-7) in hi.
// Compile-time immediates -> no standing register cost (ptxas rematerializes).
__device__ constexpr unsigned long long GXC[8] = {
    0xC0E00000C1000000ULL,  // (-8, -7)
    0xC0A00000C0C00000ULL,  // (-6, -5)
    0xC0400000C0800000ULL,  // (-4, -3)
    0xBF800000C0000000ULL,  // (-2, -1)
    0x3F80000000000000ULL,  // ( 0,  1)
    0x4040000040000000ULL,  // ( 2,  3)
    0x40A0000040800000ULL,  // ( 4,  5)
    0x40E0000040C00000ULL,  // ( 6,  7)
};
constexpr unsigned long long EPS2C = 0x0DA24260'0DA24260ULL;  // (1e-30f, 1e-30f)
}

// ---- packed dual-fp32 helpers (SASS FFMA2/FMUL2; two independent IEEE fp32 ops) ----
typedef unsigned long long u64;
__device__ __forceinline__ u64 pk2(float lo, float hi) {
    u64 d; asm("mov.b64 %0, {%1, %2};" : "=l"(d) : "f"(lo), "f"(hi)); return d;
}
__device__ __forceinline__ void upk2(u64 d, float& lo, float& hi) {
    asm("mov.b64 {%0, %1}, %2;" : "=f"(lo), "=f"(hi) : "l"(d));
}
__device__ __forceinline__ u64 fma2(u64 a, u64 b, u64 c) {
    u64 d; asm("fma.rn.f32x2 %0, %1, %2, %3;" : "=l"(d) : "l"(a), "l"(b), "l"(c)); return d;
}
__device__ __forceinline__ u64 mul2(u64 a, u64 b) {
    u64 d; asm("mul.rn.f32x2 %0, %1, %2;" : "=l"(d) : "l"(a), "l"(b)); return d;
}

// 2 CTAs per residue (half = low/high 8 y-planes), 128 threads each.
// (128,7): 148*7 = 1036 concurrent CTAs >= 1024 grid -> single wave.
__global__ __launch_bounds__(128, 7)
void pp_kernel(const float* __restrict__ C,
               const int*   __restrict__ Lw,     // int32 view of L (int32 OR int64 storage)
               const float* __restrict__ amask,
               const float* __restrict__ amber,
               float* __restrict__ out)
{
    const int rn   = blockIdx.x >> 1;
    const int half = blockIdx.x & 1;
    const int t    = threadIdx.x;       // local column: y_lo = t>>4, v = t&15

    __shared__ float4 s_atom[NA];       // x,y,z,charge

    const float* Cr = C + (size_t)rn * NA * 3;

    // ---- atom + charge load (threads 0..13) ----
    if (t < NA) {
        // Detect int64-vs-int32 storage of L (values in [-1,20]): for int64 (LE)
        // every odd 32-bit word is 0 or -1; misdetect prob for int32 ~21^-16.
        int bad = 0;
        #pragma unroll
        for (int k = 0; k < 16; ++k) {
            int hv = __ldg(Lw + 2 * k + 1);
            bad |= (hv != 0) & (hv != -1);
        }
        int lv = bad ? __ldg(Lw + rn) : __ldg(Lw + 2 * rn);
        int lc = (lv == -1) ? 20 : lv;       // X_LBL = 20
        float q = __ldg(amber + lc * NA + t) * __ldg(amask + (size_t)rn * NA + t);
        s_atom[t] = make_float4(__ldg(Cr + 3 * t),
                                __ldg(Cr + 3 * t + 1),
                                __ldg(Cr + 3 * t + 2), q);
    }

    // ---- frame build (redundant per thread; broadcast loads; block-uniform) ----
    float n0 = __ldg(Cr + 0), n1 = __ldg(Cr + 1), n2 = __ldg(Cr + 2);
    float a0 = __ldg(Cr + 3), a1 = __ldg(Cr + 4), a2 = __ldg(Cr + 5);
    float c0 = __ldg(Cr + 6), c1 = __ldg(Cr + 7), c2 = __ldg(Cr + 8);

    float b1x = a0 - n0, b1y = a1 - n1, b1z = a2 - n2;
    float b2x = c0 - a0, b2y = c1 - a1, b2z = c2 - a2;
    float b3x = b1y * b2z - b1z * b2y;
    float b3y = b1z * b2x - b1x * b2z;
    float b3z = b1x * b2y - b1y * b2x;
    float cb0 = a0 - 0.58273431f * b2x + 0.56802827f * b1x - 0.54067466f * b3x;
    float cb1 = a1 - 0.58273431f * b2y + 0.56802827f * b1y - 0.54067466f * b3y;
    float cb2 = a2 - 0.58273431f * b2z + 0.56802827f * b1z - 0.54067466f * b3z;

    float yx = cb0 - a0, yy = cb1 - a1, yz = cb2 - a2;
    float yn = sqrtf(yx * yx + yy * yy + yz * yz);
    float yi = 1.0f / fmaxf(yn, 1e-6f);
    float yux = yx * yi, yuy = yy * yi, yuz = yz * yi;

    // scalar projection subtracted from every component (replicates reference)
    float xrx = c0 - n0, xry = c1 - n1, xrz = c2 - n2;
    float xp = xrx * yux + xry * yuy + xrz * yuz;
    float xx = xrx - xp, xy = xry - xp, xz = xrz - xp;
    float xn = sqrtf(xx * xx + xy * xy + xz * xz);
    float xi = 1.0f / fmaxf(xn, 1e-6f);
    float xux = xx * xi, xuy = xy * xi, xuz = xz * xi;

    float zux = xuy * yuz - xuz * yuy;
    float zuy = xuz * yux - xux * yuz;
    float zuz = xux * yuy - xuy * yux;

    if (half == 0 && t == 0) {
        float* bb = out + BB_BASE + (size_t)rn * 12;
        bb[0] = n0;  bb[1] = n1;  bb[2] = n2;
        bb[3] = a0;  bb[4] = a1;  bb[5] = a2;
        bb[6] = c0;  bb[7] = c1;  bb[8] = c2;
        bb[9] = cb0; bb[10] = cb1; bb[11] = cb2;
        float* fr = out + FR_BASE + (size_t)rn * 9;
        fr[0] = xux; fr[1] = xuy; fr[2] = xuz;
        fr[3] = yux; fr[4] = yuy; fr[5] = yuz;
        fr[6] = zux; fr[7] = zuy; fr[8] = zuz;
    }

    __syncthreads();

    // ---- per-thread voxel column base for (y,v); x varies in registers ----
    const int   yidx = half * 8 + (t >> 4);
    const float gy = (float)yidx - 4.0f;       // VY/4
    const float gz = (float)(t & 15) - 8.0f;   // VZ/2
    float px = cb0 + gy * yux + gz * zux;
    float py = cb1 + gy * yuy + gz * zuy;
    float pz = cb2 + gy * yuz + gz * zuz;

    // packed broadcast of the x-axis (block-uniform)
    const u64 xux2 = pk2(xux, xux), xuy2 = pk2(xuy, xuy), xuz2 = pk2(xuz, xuz);

    u64 Fx2[8], Fy2[8], Fz2[8];
    #pragma unroll
    for (int j = 0; j < 8; ++j) { Fx2[j] = 0ull; Fy2[j] = 0ull; Fz2[j] = 0ull; }

    // hot loop: 14 atoms x 8 packed x-pairs, FULLY UNROLLED so ptxas can
    // batch the 14 LDS.128s and interleave atom k+1's d/r2 FMAs under atom
    // k's rsqrt latency. Weight math identical to the R5 kernel:
    //   1/(d*max(d,1)^2) = ry * sat(ry^2), ry = rsqrt(r2 + 1e-30)
    #pragma unroll
    for (int a = 0; a < NA; ++a) {
        float4 at = s_atom[a];
        float qx = px - at.x, qy = py - at.y, qz = pz - at.z;
        const u64 qx2 = pk2(qx, qx), qy2 = pk2(qy, qy), qz2 = pk2(qz, qz);
        const float w0 = at.w;
        #pragma unroll
        for (int j = 0; j < 8; ++j) {
            u64 dx2 = fma2(GXC[j], xux2, qx2);
            u64 dy2 = fma2(GXC[j], xuy2, qy2);
            u64 dz2 = fma2(GXC[j], xuz2, qz2);
            u64 r22 = fma2(dx2, dx2, fma2(dy2, dy2, fma2(dz2, dz2, EPS2C)));
            float ra, rb; upk2(r22, ra, rb);
            float rya = rsqrtf(ra), ryb = rsqrtf(rb);
            float wa = w0 * (rya * __saturatef(rya * rya));
            float wb = w0 * (ryb * __saturatef(ryb * ryb));
            u64 wp = pk2(wa, wb);
            Fx2[j] = fma2(wp, dx2, Fx2[j]);
            Fy2[j] = fma2(wp, dy2, Fy2[j]);
            Fz2[j] = fma2(wp, dz2, Fz2[j]);
        }
    }

    // ---- normalize field vectors (packed) ----
    #pragma unroll
    for (int j = 0; j < 8; ++j) {
        u64 s2 = fma2(Fx2[j], Fx2[j], fma2(Fy2[j], Fy2[j], mul2(Fz2[j], Fz2[j])));
        float sa, sb; upk2(s2, sa, sb);
        float sca = (sa > 0.0f) ? rsqrtf(sa) : 1.0f;
        float scb = (sb > 0.0f) ? rsqrtf(sb) : 1.0f;
        u64 sc2 = pk2(sca, scb);
        Fx2[j] = mul2(Fx2[j], sc2);
        Fy2[j] = mul2(Fy2[j], sc2);
        Fz2[j] = mul2(Fz2[j], sc2);
    }

    // unpack to scalars for the finite difference
    float Fx[VOX], Fy[VOX], Fz[VOX];
    #pragma unroll
    for (int j = 0; j < 8; ++j) {
        upk2(Fx2[j], Fx[2 * j], Fx[2 * j + 1]);
        upk2(Fy2[j], Fy[2 * j], Fy[2 * j + 1]);
        upk2(Fz2[j], Fz[2 * j], Fz[2 * j + 1]);
    }

    // ---- divergence: all components differenced along the VX axis (axis 2),
    //      x: flip_last=False, y/z: flip_last=True (matches reference) ----
    float* dv = out + DIV_BASE + (size_t)rn * VOXELS + (half * 128 + t);
    dv[0] = (Fx[1] - Fx[0]) + (Fy[1] - Fy[0]) + (Fz[1] - Fz[0]);
    #pragma unroll
    for (int i = 1; i < VOX - 1; ++i) {
        float d = 0.5f * (Fx[i + 1] - Fx[i - 1])
                + 0.5f * (Fy[i + 1] - Fy[i - 1])
                + 0.5f * (Fz[i + 1] - Fz[i - 1]);
        dv[i * 256] = d;
    }
    dv[15 * 256] = (Fx[15] - Fx[14]) + (Fy[14] - Fy[15]) + (Fz[14] - Fz[15]);
}

extern "C" void kernel_launch(void* const* d_in, const int* in_sizes, int n_in,
                              void* d_out, int out_size)
{
    const float* C     = (const float*)d_in[0];
    const int*   Lw    = (const int*)  d_in[1];   // int32 view; width auto-detected
    const float* amask = (const float*)d_in[2];
    // d_in[3] = valid_mask: unused by the reference
    const float* amber = (const float*)d_in[4];

    pp_kernel<<<ZN * 2, 128>>>(C, Lw, amask, amber, (float*)d_out);
}